// round 8
// baseline (speedup 1.0000x reference)
#include <cuda_runtime.h>
#include <cuda_fp16.h>
#include <cstdint>

// Problem constants: N=100000, F=512, H=16, C=40, E=3200000
#define NMAX 100000
#define EMAX 3200000
#define FDIM 512
#define HDIM 16
#define CDIM 40
#define NBMAX 128           // >= ceil(NMAX/1024)

// ---- scratch (static device globals; no allocation allowed) ----
__device__ int     g_is64;
__device__ int     g_deg[NMAX];
__device__ int     g_rowptr[NMAX];
__device__ int     g_cursor[NMAX];
__device__ int     g_bsum[NBMAX];
__device__ int     g_boff[NBMAX];
__device__ float   g_dinv[NMAX];
__device__ int     g_csr[EMAX];        // src ids grouped by dst
__device__ __half2 g_h [NMAX * 8];     // fp16 dinv-scaled hidden, layer 1
__device__ __half2 g_h2[NMAX * 8];     // fp16 dinv-scaled hidden, layer 2

// ---- f32x2 packed-math helpers (sm_103a) ----
__device__ __forceinline__ unsigned long long f2_fma(
    unsigned long long a, unsigned long long b, unsigned long long c) {
    unsigned long long d;
    asm("fma.rn.f32x2 %0, %1, %2, %3;" : "=l"(d) : "l"(a), "l"(b), "l"(c));
    return d;
}
__device__ __forceinline__ unsigned long long f2_add(
    unsigned long long a, unsigned long long b) {
    unsigned long long d;
    asm("add.rn.f32x2 %0, %1, %2;" : "=l"(d) : "l"(a), "l"(b));
    return d;
}
__device__ __forceinline__ unsigned long long f2_mul(
    unsigned long long a, unsigned long long b) {
    unsigned long long d;
    asm("mul.rn.f32x2 %0, %1, %2;" : "=l"(d) : "l"(a), "l"(b));
    return d;
}
__device__ __forceinline__ unsigned long long f2_pack(float lo, float hi) {
    unsigned long long d;
    asm("mov.b64 %0, {%1, %2};" : "=l"(d) : "f"(lo), "f"(hi));
    return d;
}

__device__ __forceinline__ int dec_src(const void* ei, int E, int e) {
    return g_is64 ? (int)((const long long*)ei)[e] : ((const int*)ei)[e];
}
__device__ __forceinline__ int dec_dst(const void* ei, int E, int e) {
    return g_is64 ? (int)((const long long*)ei)[(size_t)E + e]
                  : ((const int*)ei)[E + e];
}

// ---------------------------------------------------------------
__global__ void k_init(const int* __restrict__ ei, int N) {
    int i = blockIdx.x * blockDim.x + threadIdx.x;
    if (i < N) g_deg[i] = 0;
    if (i == 0) {
        int any = 0;
        #pragma unroll
        for (int q = 1; q < 256; q += 2) any |= ei[q];
        g_is64 = (any == 0) ? 1 : 0;
    }
}

__global__ __launch_bounds__(256) void k_deg(const void* __restrict__ ei, int E) {
    int e = blockIdx.x * blockDim.x + threadIdx.x;
    if (e >= E) return;
    atomicAdd(&g_deg[dec_dst(ei, E, e)], 1);
}

// ---- 3-phase parallel exclusive scan of g_deg -> g_rowptr/g_cursor ----
// Phase A: per-1024-node block sums (grid NB, block 256).
__global__ __launch_bounds__(256) void k_scanA(int N) {
    __shared__ int sh[8];
    int b = blockIdx.x, t = threadIdx.x;
    int s = 0;
    #pragma unroll
    for (int q = 0; q < 4; q++) {
        int i = b * 1024 + q * 256 + t;
        if (i < N) s += g_deg[i];
    }
    #pragma unroll
    for (int off = 16; off; off >>= 1)
        s += __shfl_xor_sync(0xffffffffu, s, off);
    if ((t & 31) == 0) sh[t >> 5] = s;
    __syncthreads();
    if (t == 0) {
        int tot = 0;
        #pragma unroll
        for (int w = 0; w < 8; w++) tot += sh[w];
        g_bsum[b] = tot;
    }
}

// Phase B: single block scans NB block sums (exclusive).
__global__ __launch_bounds__(128) void k_scanB(int NB) {
    __shared__ int sh[128];
    int t = threadIdx.x;
    int v = (t < NB) ? g_bsum[t] : 0;
    sh[t] = v;
    __syncthreads();
    for (int off = 1; off < 128; off <<= 1) {
        int u = (t >= off) ? sh[t - off] : 0;
        __syncthreads();
        sh[t] += u;
        __syncthreads();
    }
    if (t < NB) g_boff[t] = sh[t] - v;   // exclusive
}

// Phase C: per-block shared scan + offset (grid NB, block 1024).
__global__ __launch_bounds__(1024) void k_scanC(int N) {
    __shared__ int sh[1024];
    int b = blockIdx.x, t = threadIdx.x;
    int i = b * 1024 + t;
    int d = (i < N) ? g_deg[i] : 0;
    sh[t] = d;
    __syncthreads();
    for (int off = 1; off < 1024; off <<= 1) {
        int u = (t >= off) ? sh[t - off] : 0;
        __syncthreads();
        sh[t] += u;
        __syncthreads();
    }
    if (i < N) {
        int excl = sh[t] - d + g_boff[b];
        g_rowptr[i] = excl;
        g_cursor[i] = excl;
    }
}

__global__ void k_dinv(int N) {
    int i = blockIdx.x * blockDim.x + threadIdx.x;
    if (i < N) g_dinv[i] = rsqrtf((float)(g_deg[i] + 1));  // +1 self-loop
}

__global__ __launch_bounds__(256) void k_fill(const void* __restrict__ ei, int E) {
    int e = blockIdx.x * blockDim.x + threadIdx.x;
    if (e >= E) return;
    int s = dec_src(ei, E, e);
    int d = dec_dst(ei, E, e);
    int pos = atomicAdd(&g_cursor[d], 1);
    g_csr[pos] = s;
}

// ---------------------------------------------------------------
// GEMM1 + scale epilogue:  g_h[i,:] = fp16( dinv[i] * (x[i,:] @ W1) )
// Exact R3/R7 structure (do not perturb): 8 warps/block, 4 rows/warp,
// scalar coalesced x loads, f32x2 accumulators, W1 in shared as float2
// j-pairs with odd pitch, value-halving butterfly tail.
#define WPITCH 513
__global__ __launch_bounds__(256, 2) void k_gemm1(
    const float* __restrict__ x, const float* __restrict__ W1, int N)
{
    __shared__ unsigned long long wS[8 * WPITCH];
    {
        const unsigned long long* gw = (const unsigned long long*)W1;
        for (int idx = threadIdx.x; idx < FDIM * 8; idx += 256) {
            int k = idx >> 3, j2 = idx & 7;
            wS[j2 * WPITCH + k] = gw[idx];
        }
    }
    __syncthreads();

    int warp = threadIdx.x >> 5;
    int lane = threadIdx.x & 31;
    int r0 = blockIdx.x * 32 + warp * 4;

    unsigned long long acc[4][8];
    #pragma unroll
    for (int r = 0; r < 4; r++)
        #pragma unroll
        for (int j = 0; j < 8; j++) acc[r][j] = 0ull;

    bool v0 = (r0 + 0) < N, v1 = (r0 + 1) < N, v2 = (r0 + 2) < N, v3 = (r0 + 3) < N;
    const float* x0p = x + (size_t)(r0 + 0) * FDIM + lane;
    const float* x1p = x + (size_t)(r0 + 1) * FDIM + lane;
    const float* x2p = x + (size_t)(r0 + 2) * FDIM + lane;
    const float* x3p = x + (size_t)(r0 + 3) * FDIM + lane;

    #pragma unroll 4
    for (int i = 0; i < 16; i++) {
        int k = lane + 32 * i;
        float x0 = v0 ? x0p[32 * i] : 0.0f;
        float x1 = v1 ? x1p[32 * i] : 0.0f;
        float x2 = v2 ? x2p[32 * i] : 0.0f;
        float x3 = v3 ? x3p[32 * i] : 0.0f;
        unsigned long long p0 = f2_pack(x0, x0);
        unsigned long long p1 = f2_pack(x1, x1);
        unsigned long long p2 = f2_pack(x2, x2);
        unsigned long long p3 = f2_pack(x3, x3);
        #pragma unroll
        for (int j = 0; j < 8; j++) {
            unsigned long long wv = wS[j * WPITCH + k];
            acc[0][j] = f2_fma(p0, wv, acc[0][j]);
            acc[1][j] = f2_fma(p1, wv, acc[1][j]);
            acc[2][j] = f2_fma(p2, wv, acc[2][j]);
            acc[3][j] = f2_fma(p3, wv, acc[3][j]);
        }
    }

    unsigned long long v[32];
    #pragma unroll
    for (int r = 0; r < 4; r++)
        #pragma unroll
        for (int j = 0; j < 8; j++) v[r * 8 + j] = acc[r][j];

    #pragma unroll
    for (int s = 0; s < 5; s++) {
        const int m = 1 << s;
        const int half = 16 >> s;
        bool up = (lane & m) != 0;
        #pragma unroll
        for (int q = 0; q < 16; q++) {
            if (q < half) {
                unsigned long long keep = up ? v[q + half] : v[q];
                unsigned long long mine = up ? v[q] : v[q + half];
                unsigned long long got = __shfl_xor_sync(0xffffffffu, mine, m);
                v[q] = f2_add(keep, got);
            }
        }
    }

    int p = ((lane & 1) << 4) | ((lane & 2) << 2) | (lane & 4) |
            ((lane & 8) >> 2) | ((lane & 16) >> 4);
    int r = p >> 3, j2 = p & 7;
    int row = r0 + r;
    if (row < N) {
        float dv = g_dinv[row];
        unsigned long long res = f2_mul(v[0], f2_pack(dv, dv));
        float2 rf = *(float2*)&res;
        g_h[(size_t)row * 8 + j2] = __float22half2_rn(rf);
    }
}

// ---------------------------------------------------------------
// Pull-prop layer 1 + mid epilogue. One warp per dst node.
// lane = grp*4+c is NOT the layout: c = lane&3 (8B chunk of the 32B
// fp16 row), grp = lane>>2 (source slot, 8-way). No atomics.
// h2[d] = fp16( dinv * relu(dinv*(sum + self) + b1) )
__global__ __launch_bounds__(256) void k_prop1(const float* __restrict__ b1, int N) {
    int wg = (blockIdx.x * 256 + threadIdx.x) >> 5;
    if (wg >= N) return;
    int lane = threadIdx.x & 31;
    int c = lane & 3, grp = lane >> 2;
    int d = wg;
    int start = g_rowptr[d];
    int cnt = g_deg[d];
    const uint2* hin = (const uint2*)g_h;

    float4 a0 = make_float4(0.f, 0.f, 0.f, 0.f);
    float4 a1 = make_float4(0.f, 0.f, 0.f, 0.f);
    for (int base = 0; base < cnt; base += 16) {
        int i0 = base + grp, i1 = base + 8 + grp;
        if (i0 < cnt) {
            uint2 hv = hin[(size_t)g_csr[start + i0] * 4 + c];
            float2 f0 = __half22float2(*(__half2*)&hv.x);
            float2 f1 = __half22float2(*(__half2*)&hv.y);
            a0.x += f0.x; a0.y += f0.y; a0.z += f1.x; a0.w += f1.y;
        }
        if (i1 < cnt) {
            uint2 hv = hin[(size_t)g_csr[start + i1] * 4 + c];
            float2 f0 = __half22float2(*(__half2*)&hv.x);
            float2 f1 = __half22float2(*(__half2*)&hv.y);
            a1.x += f0.x; a1.y += f0.y; a1.z += f1.x; a1.w += f1.y;
        }
    }
    a0.x += a1.x; a0.y += a1.y; a0.z += a1.z; a0.w += a1.w;

    #pragma unroll
    for (int off = 16; off >= 4; off >>= 1) {
        a0.x += __shfl_xor_sync(0xffffffffu, a0.x, off);
        a0.y += __shfl_xor_sync(0xffffffffu, a0.y, off);
        a0.z += __shfl_xor_sync(0xffffffffu, a0.z, off);
        a0.w += __shfl_xor_sync(0xffffffffu, a0.w, off);
    }

    if (lane < 4) {
        uint2 sv = hin[(size_t)d * 4 + lane];
        float2 s0 = __half22float2(*(__half2*)&sv.x);
        float2 s1 = __half22float2(*(__half2*)&sv.y);
        float dv = g_dinv[d];
        float4 bb = ((const float4*)b1)[lane];
        float2 r0, r1;
        r0.x = fmaxf(dv * (a0.x + s0.x) + bb.x, 0.f) * dv;
        r0.y = fmaxf(dv * (a0.y + s0.y) + bb.y, 0.f) * dv;
        r1.x = fmaxf(dv * (a0.z + s1.x) + bb.z, 0.f) * dv;
        r1.y = fmaxf(dv * (a0.w + s1.y) + bb.w, 0.f) * dv;
        uint2 outv;
        *(__half2*)&outv.x = __float22half2_rn(r0);
        *(__half2*)&outv.y = __float22half2_rn(r1);
        ((uint2*)g_h2)[(size_t)d * 4 + lane] = outv;
    }
}

// ---------------------------------------------------------------
// Pull-prop layer 2 + output epilogue (logits @ W2 + b2, softmax).
// d_out[0:N*40) = softmax ; d_out[N*40:2N*40) = logits.
__global__ __launch_bounds__(256) void k_prop2out(
    const float* __restrict__ W2, const float* __restrict__ b2,
    float* __restrict__ dout, int N, int write_h)
{
    __shared__ float w[HDIM * CDIM];
    __shared__ float bs[CDIM];
    for (int i = threadIdx.x; i < HDIM * CDIM; i += 256) w[i] = W2[i];
    if (threadIdx.x < CDIM) bs[threadIdx.x] = b2[threadIdx.x];
    __syncthreads();

    int wg = (blockIdx.x * 256 + threadIdx.x) >> 5;
    if (wg >= N) return;
    int lane = threadIdx.x & 31;
    int c = lane & 3, grp = lane >> 2;
    int d = wg;
    int start = g_rowptr[d];
    int cnt = g_deg[d];
    const uint2* hin = (const uint2*)g_h2;

    float4 a0 = make_float4(0.f, 0.f, 0.f, 0.f);
    float4 a1 = make_float4(0.f, 0.f, 0.f, 0.f);
    for (int base = 0; base < cnt; base += 16) {
        int i0 = base + grp, i1 = base + 8 + grp;
        if (i0 < cnt) {
            uint2 hv = hin[(size_t)g_csr[start + i0] * 4 + c];
            float2 f0 = __half22float2(*(__half2*)&hv.x);
            float2 f1 = __half22float2(*(__half2*)&hv.y);
            a0.x += f0.x; a0.y += f0.y; a0.z += f1.x; a0.w += f1.y;
        }
        if (i1 < cnt) {
            uint2 hv = hin[(size_t)g_csr[start + i1] * 4 + c];
            float2 f0 = __half22float2(*(__half2*)&hv.x);
            float2 f1 = __half22float2(*(__half2*)&hv.y);
            a1.x += f0.x; a1.y += f0.y; a1.z += f1.x; a1.w += f1.y;
        }
    }
    a0.x += a1.x; a0.y += a1.y; a0.z += a1.z; a0.w += a1.w;

    #pragma unroll
    for (int off = 16; off >= 4; off >>= 1) {
        a0.x += __shfl_xor_sync(0xffffffffu, a0.x, off);
        a0.y += __shfl_xor_sync(0xffffffffu, a0.y, off);
        a0.z += __shfl_xor_sync(0xffffffffu, a0.z, off);
        a0.w += __shfl_xor_sync(0xffffffffu, a0.w, off);
    }

    // add self + scale (every lane holds its chunk-c partials)
    {
        uint2 sv = hin[(size_t)d * 4 + c];
        float2 s0 = __half22float2(*(__half2*)&sv.x);
        float2 s1 = __half22float2(*(__half2*)&sv.y);
        float dv = g_dinv[d];
        a0.x = dv * (a0.x + s0.x);
        a0.y = dv * (a0.y + s0.y);
        a0.z = dv * (a0.z + s1.x);
        a0.w = dv * (a0.w + s1.y);
    }

    // broadcast the 16-vector (chunk q lives on lane q, grp=0)
    float row[HDIM];
    #pragma unroll
    for (int q = 0; q < 4; q++) {
        row[q * 4 + 0] = __shfl_sync(0xffffffffu, a0.x, q);
        row[q * 4 + 1] = __shfl_sync(0xffffffffu, a0.y, q);
        row[q * 4 + 2] = __shfl_sync(0xffffffffu, a0.z, q);
        row[q * 4 + 3] = __shfl_sync(0xffffffffu, a0.w, q);
    }

    // logits: lane -> class lane, and class 32+lane for lanes 0..7
    float l0 = bs[lane];
    bool has2 = lane < (CDIM - 32);
    float l1 = has2 ? bs[32 + lane] : -1e30f;
    #pragma unroll
    for (int k = 0; k < HDIM; k++) {
        float v = row[k];
        l0 += v * w[k * CDIM + lane];
        if (has2) l1 += v * w[k * CDIM + 32 + lane];
    }

    float m = fmaxf(l0, l1);
    #pragma unroll
    for (int off = 16; off; off >>= 1)
        m = fmaxf(m, __shfl_xor_sync(0xffffffffu, m, off));
    float e0 = __expf(l0 - m);
    float e1 = has2 ? __expf(l1 - m) : 0.0f;
    float s = e0 + e1;
    #pragma unroll
    for (int off = 16; off; off >>= 1)
        s += __shfl_xor_sync(0xffffffffu, s, off);
    float inv = 1.0f / s;

    float* so = dout + (size_t)d * CDIM;
    so[lane] = e0 * inv;
    if (has2) so[32 + lane] = e1 * inv;
    if (write_h) {
        float* ho = dout + (size_t)N * CDIM + (size_t)d * CDIM;
        ho[lane] = l0;
        if (has2) ho[32 + lane] = l1;
    }
}

// ---------------------------------------------------------------
extern "C" void kernel_launch(void* const* d_in, const int* in_sizes, int n_in,
                              void* d_out, int out_size)
{
    // metadata order: x, edge_index, num_nodes, W1, b1, W2, b2
    const float* x  = (const float*)d_in[0];
    const void*  ei = d_in[1];
    const float* W1 = (const float*)d_in[3];
    const float* b1 = (const float*)d_in[4];
    const float* W2 = (const float*)d_in[5];
    const float* b2 = (const float*)d_in[6];
    float* out = (float*)d_out;

    int N = in_sizes[0] / FDIM;
    int E = in_sizes[1] / 2;
    if (N > NMAX) N = NMAX;
    if (E > EMAX) E = EMAX;
    int write_h = (out_size >= 2 * N * CDIM) ? 1 : 0;

    const int B = 256;
    int NB = (N + 1023) / 1024;
    int nodeWarpBlocks = (N * 32 + B - 1) / B;

    k_init<<<(N + B - 1) / B, B>>>((const int*)ei, N);
    k_deg<<<(E + B - 1) / B, B>>>(ei, E);
    k_scanA<<<NB, 256>>>(N);
    k_scanB<<<1, 128>>>(NB);
    k_scanC<<<NB, 1024>>>(N);
    k_dinv<<<(N + B - 1) / B, B>>>(N);
    k_fill<<<(E + B - 1) / B, B>>>(ei, E);

    k_gemm1<<<(N + 31) / 32, 256>>>(x, W1, N);

    k_prop1<<<nodeWarpBlocks, B>>>(b1, N);
    k_prop2out<<<nodeWarpBlocks, B>>>(W2, b2, out, N, write_h);
}

// round 9
// speedup vs baseline: 1.3906x; 1.3906x over previous
#include <cuda_runtime.h>
#include <cuda_fp16.h>
#include <cstdint>

// Problem constants: N=100000, F=512, H=16, C=40, E=3200000
#define NMAX 100000
#define EMAX 3200000
#define FDIM 512
#define HDIM 16
#define CDIM 40

// ---- scratch (static device globals; no allocation allowed) ----
// All node-feature tables are fp16 rows of 32B (2 x uint4 chunks).
__device__ int    g_is64;
__device__ int2   g_edge[EMAX];      // (src, dst)
__device__ int    g_deg[NMAX];
__device__ float  g_dinv[NMAX];
__device__ uint4  g_h   [NMAX * 2];  // fp16 scaled hidden L1 (gather table)
__device__ uint4  g_h2  [NMAX * 2];  // fp16 scaled hidden L2 (gather table)
__device__ uint4  g_agg1[NMAX * 2];  // fp16 accumulator L1 (init = g_h row)
__device__ uint4  g_agg2[NMAX * 2];  // fp16 accumulator L2 (init = g_h2 row)

// ---- f32x2 packed-math helpers (sm_103a) ----
__device__ __forceinline__ unsigned long long f2_fma(
    unsigned long long a, unsigned long long b, unsigned long long c) {
    unsigned long long d;
    asm("fma.rn.f32x2 %0, %1, %2, %3;" : "=l"(d) : "l"(a), "l"(b), "l"(c));
    return d;
}
__device__ __forceinline__ unsigned long long f2_add(
    unsigned long long a, unsigned long long b) {
    unsigned long long d;
    asm("add.rn.f32x2 %0, %1, %2;" : "=l"(d) : "l"(a), "l"(b));
    return d;
}
__device__ __forceinline__ unsigned long long f2_mul(
    unsigned long long a, unsigned long long b) {
    unsigned long long d;
    asm("mul.rn.f32x2 %0, %1, %2;" : "=l"(d) : "l"(a), "l"(b));
    return d;
}
__device__ __forceinline__ unsigned long long f2_pack(float lo, float hi) {
    unsigned long long d;
    asm("mov.b64 %0, {%1, %2};" : "=l"(d) : "f"(lo), "f"(hi));
    return d;
}

// ---------------------------------------------------------------
__global__ void k_init(const int* __restrict__ ei, int N) {
    int i = blockIdx.x * blockDim.x + threadIdx.x;
    if (i < N) g_deg[i] = 0;
    if (i == 0) {
        int any = 0;
        #pragma unroll
        for (int q = 1; q < 256; q += 2) any |= ei[q];
        g_is64 = (any == 0) ? 1 : 0;
    }
}

// Normalize edges to packed int2 and count in-degree (dst side).
__global__ __launch_bounds__(256) void k_convert(const void* __restrict__ ei, int E) {
    int e = blockIdx.x * blockDim.x + threadIdx.x;
    if (e >= E) return;
    int s, d;
    if (g_is64) {
        const long long* p = (const long long*)ei;
        s = (int)p[e];
        d = (int)p[(long long)E + e];
    } else {
        const int* p = (const int*)ei;
        s = p[e];
        d = p[E + e];
    }
    g_edge[e] = make_int2(s, d);
    atomicAdd(&g_deg[d], 1);
}

__global__ void k_dinv(int N) {
    int i = blockIdx.x * blockDim.x + threadIdx.x;
    if (i < N) g_dinv[i] = rsqrtf((float)(g_deg[i] + 1));  // +1 self-loop
}

// ---------------------------------------------------------------
// GEMM1 + scale epilogue:  hs[i,:] = dinv[i] * (x[i,:] @ W1)
// Exact R3/R7 proven structure (75us): 8 warps/block, 4 rows/warp,
// scalar coalesced x loads, f32x2 accumulators, W1 in shared as float2
// j-pairs with odd pitch, value-halving butterfly tail. Epilogue writes
// the fp16 j-pair (4B) to g_h and g_agg1 (self-loop init).
#define WPITCH 513
__global__ __launch_bounds__(256, 2) void k_gemm1(
    const float* __restrict__ x, const float* __restrict__ W1, int N)
{
    __shared__ unsigned long long wS[8 * WPITCH];
    {
        const unsigned long long* gw = (const unsigned long long*)W1;
        for (int idx = threadIdx.x; idx < FDIM * 8; idx += 256) {
            int k = idx >> 3, j2 = idx & 7;
            wS[j2 * WPITCH + k] = gw[idx];
        }
    }
    __syncthreads();

    int warp = threadIdx.x >> 5;
    int lane = threadIdx.x & 31;
    int r0 = blockIdx.x * 32 + warp * 4;

    unsigned long long acc[4][8];
    #pragma unroll
    for (int r = 0; r < 4; r++)
        #pragma unroll
        for (int j = 0; j < 8; j++) acc[r][j] = 0ull;

    bool v0 = (r0 + 0) < N, v1 = (r0 + 1) < N, v2 = (r0 + 2) < N, v3 = (r0 + 3) < N;
    const float* x0p = x + (size_t)(r0 + 0) * FDIM + lane;
    const float* x1p = x + (size_t)(r0 + 1) * FDIM + lane;
    const float* x2p = x + (size_t)(r0 + 2) * FDIM + lane;
    const float* x3p = x + (size_t)(r0 + 3) * FDIM + lane;

    #pragma unroll 4
    for (int i = 0; i < 16; i++) {
        int k = lane + 32 * i;
        float x0 = v0 ? x0p[32 * i] : 0.0f;
        float x1 = v1 ? x1p[32 * i] : 0.0f;
        float x2 = v2 ? x2p[32 * i] : 0.0f;
        float x3 = v3 ? x3p[32 * i] : 0.0f;
        unsigned long long p0 = f2_pack(x0, x0);
        unsigned long long p1 = f2_pack(x1, x1);
        unsigned long long p2 = f2_pack(x2, x2);
        unsigned long long p3 = f2_pack(x3, x3);
        #pragma unroll
        for (int j = 0; j < 8; j++) {
            unsigned long long wv = wS[j * WPITCH + k];
            acc[0][j] = f2_fma(p0, wv, acc[0][j]);
            acc[1][j] = f2_fma(p1, wv, acc[1][j]);
            acc[2][j] = f2_fma(p2, wv, acc[2][j]);
            acc[3][j] = f2_fma(p3, wv, acc[3][j]);
        }
    }

    unsigned long long v[32];
    #pragma unroll
    for (int r = 0; r < 4; r++)
        #pragma unroll
        for (int j = 0; j < 8; j++) v[r * 8 + j] = acc[r][j];

    #pragma unroll
    for (int s = 0; s < 5; s++) {
        const int m = 1 << s;
        const int half = 16 >> s;
        bool up = (lane & m) != 0;
        #pragma unroll
        for (int q = 0; q < 16; q++) {
            if (q < half) {
                unsigned long long keep = up ? v[q + half] : v[q];
                unsigned long long mine = up ? v[q] : v[q + half];
                unsigned long long got = __shfl_xor_sync(0xffffffffu, mine, m);
                v[q] = f2_add(keep, got);
            }
        }
    }

    int p = ((lane & 1) << 4) | ((lane & 2) << 2) | (lane & 4) |
            ((lane & 8) >> 2) | ((lane & 16) >> 4);
    int r = p >> 3, j2 = p & 7;
    int row = r0 + r;
    if (row < N) {
        float dv = g_dinv[row];
        unsigned long long res = f2_mul(v[0], f2_pack(dv, dv));
        float2 rf = *(float2*)&res;
        __half2 hv = __float22half2_rn(rf);
        ((__half2*)g_h)[(size_t)row * 8 + j2] = hv;
        ((__half2*)g_agg1)[(size_t)row * 8 + j2] = hv;   // self-loop init
    }
}

// ---------------------------------------------------------------
// Edge propagation: 2 threads per edge, one 16B chunk (8 halves) each.
// Pure bit transport: uint4 gather + one fp16x2 vector RED. No float
// conversion in the kernel; the adds happen in the L2 atomic ALU.
__global__ __launch_bounds__(256) void k_prop(int E, int layer) {
    int t = blockIdx.x * blockDim.x + threadIdx.x;
    int e = t >> 1;
    if (e >= E) return;
    int c = t & 1;
    const uint4* hin = layer ? g_h2 : g_h;
    uint4* out = layer ? g_agg2 : g_agg1;

    int2 sd = g_edge[e];
    uint4 v = hin[(size_t)sd.x * 2 + c];
    uint4* p = out + (size_t)sd.y * 2 + c;
    asm volatile("red.global.add.noftz.v4.f16x2 [%0], {%1, %2, %3, %4};"
                 :: "l"(p), "r"(v.x), "r"(v.y), "r"(v.z), "r"(v.w)
                 : "memory");
}

// ---------------------------------------------------------------
// Mid layer, per 16B chunk: out1 = relu(dinv*agg1 + b1); hs2 = dinv*out1
// writes g_h2 (gather table) and g_agg2 (self-loop init), both fp16.
__global__ void k_mid(const float* __restrict__ b1, int N) {
    int idx = blockIdx.x * blockDim.x + threadIdx.x;   // chunk index
    if (idx >= N * 2) return;
    int i = idx >> 1;
    int c = idx & 1;
    float dv = g_dinv[i];
    uint4 a = g_agg1[idx];
    float2 f0 = __half22float2(*(__half2*)&a.x);
    float2 f1 = __half22float2(*(__half2*)&a.y);
    float2 f2v = __half22float2(*(__half2*)&a.z);
    float2 f3 = __half22float2(*(__half2*)&a.w);
    const float4* b4 = (const float4*)b1;
    float4 bb0 = b4[c * 2 + 0];
    float4 bb1 = b4[c * 2 + 1];
    float2 r0, r1, r2, r3;
    r0.x = fmaxf(dv * f0.x + bb0.x, 0.f) * dv;
    r0.y = fmaxf(dv * f0.y + bb0.y, 0.f) * dv;
    r1.x = fmaxf(dv * f1.x + bb0.z, 0.f) * dv;
    r1.y = fmaxf(dv * f1.y + bb0.w, 0.f) * dv;
    r2.x = fmaxf(dv * f2v.x + bb1.x, 0.f) * dv;
    r2.y = fmaxf(dv * f2v.y + bb1.y, 0.f) * dv;
    r3.x = fmaxf(dv * f3.x + bb1.z, 0.f) * dv;
    r3.y = fmaxf(dv * f3.y + bb1.w, 0.f) * dv;
    uint4 o;
    *(__half2*)&o.x = __float22half2_rn(r0);
    *(__half2*)&o.y = __float22half2_rn(r1);
    *(__half2*)&o.z = __float22half2_rn(r2);
    *(__half2*)&o.w = __float22half2_rn(r3);
    g_h2[idx] = o;
    g_agg2[idx] = o;
}

// ---------------------------------------------------------------
// Output: logits = (dinv[i]*agg2[i,:]) @ W2 + b2 ; out = softmax
// d_out[0:N*40) = softmax ; d_out[N*40:2N*40) = logits
__global__ __launch_bounds__(256) void k_out(
    const float* __restrict__ W2, const float* __restrict__ b2,
    float* __restrict__ dout, int N, int write_h)
{
    __shared__ float w[HDIM * CDIM];
    __shared__ float bs[CDIM];
    for (int i = threadIdx.x; i < HDIM * CDIM; i += blockDim.x) w[i] = W2[i];
    if (threadIdx.x < CDIM) bs[threadIdx.x] = b2[threadIdx.x];
    __syncthreads();

    int i = blockIdx.x * blockDim.x + threadIdx.x;
    if (i >= N) return;

    float dv = g_dinv[i];
    float row[HDIM];
    #pragma unroll
    for (int c = 0; c < 2; c++) {
        uint4 a = g_agg2[(size_t)i * 2 + c];
        float2 f0 = __half22float2(*(__half2*)&a.x);
        float2 f1 = __half22float2(*(__half2*)&a.y);
        float2 f2v = __half22float2(*(__half2*)&a.z);
        float2 f3 = __half22float2(*(__half2*)&a.w);
        row[c * 8 + 0] = f0.x * dv; row[c * 8 + 1] = f0.y * dv;
        row[c * 8 + 2] = f1.x * dv; row[c * 8 + 3] = f1.y * dv;
        row[c * 8 + 4] = f2v.x * dv; row[c * 8 + 5] = f2v.y * dv;
        row[c * 8 + 6] = f3.x * dv; row[c * 8 + 7] = f3.y * dv;
    }

    float logit[CDIM];
    #pragma unroll
    for (int j = 0; j < CDIM; j++) logit[j] = bs[j];
    #pragma unroll
    for (int k = 0; k < HDIM; k++) {
        float v = row[k];
        const float* wr = &w[k * CDIM];
        #pragma unroll
        for (int j = 0; j < CDIM; j++) logit[j] += v * wr[j];
    }

    float mx = logit[0];
    #pragma unroll
    for (int j = 1; j < CDIM; j++) mx = fmaxf(mx, logit[j]);
    float sum = 0.0f;
    #pragma unroll
    for (int j = 0; j < CDIM; j++) sum += __expf(logit[j] - mx);
    float inv = 1.0f / sum;

    float* so = dout + (size_t)i * CDIM;
    #pragma unroll
    for (int j = 0; j < CDIM; j++) so[j] = __expf(logit[j] - mx) * inv;

    if (write_h) {
        float* ho = dout + (size_t)N * CDIM + (size_t)i * CDIM;
        #pragma unroll
        for (int j = 0; j < CDIM; j++) ho[j] = logit[j];
    }
}

// ---------------------------------------------------------------
extern "C" void kernel_launch(void* const* d_in, const int* in_sizes, int n_in,
                              void* d_out, int out_size)
{
    // metadata order: x, edge_index, num_nodes, W1, b1, W2, b2
    const float* x  = (const float*)d_in[0];
    const void*  ei = d_in[1];
    const float* W1 = (const float*)d_in[3];
    const float* b1 = (const float*)d_in[4];
    const float* W2 = (const float*)d_in[5];
    const float* b2 = (const float*)d_in[6];
    float* out = (float*)d_out;

    int N = in_sizes[0] / FDIM;
    int E = in_sizes[1] / 2;
    if (N > NMAX) N = NMAX;
    if (E > EMAX) E = EMAX;
    int write_h = (out_size >= 2 * N * CDIM) ? 1 : 0;

    const int B = 256;

    k_init<<<(N + B - 1) / B, B>>>((const int*)ei, N);
    k_convert<<<(E + B - 1) / B, B>>>(ei, E);
    k_dinv<<<(N + B - 1) / B, B>>>(N);

    k_gemm1<<<(N + 31) / 32, 256>>>(x, W1, N);

    k_prop<<<((size_t)E * 2 + B - 1) / B, B>>>(E, 0);
    k_mid<<<(N * 2 + B - 1) / B, B>>>(b1, N);
    k_prop<<<((size_t)E * 2 + B - 1) / B, B>>>(E, 1);

    k_out<<<(N + B - 1) / B, B>>>(W2, b2, out, N, write_h);
}

// round 10
// speedup vs baseline: 1.4288x; 1.0275x over previous
#include <cuda_runtime.h>
#include <cuda_fp16.h>
#include <cstdint>

// Problem constants: N=100000, F=512, H=16, C=40, E=3200000
#define NMAX 100000
#define EMAX 3200000
#define FDIM 512
#define HDIM 16
#define CDIM 40

// ---- scratch (static device globals; no allocation allowed) ----
__device__ int    g_is64;
__device__ int2   g_edge[EMAX];      // (src, dst)
__device__ int    g_deg[NMAX];
__device__ float2 g_hraw[NMAX * 8];  // fp32 raw x@W1 (pre-scale)
__device__ uint4  g_h   [NMAX * 2];  // fp16 scaled hidden L1 (gather table)
__device__ uint4  g_h2  [NMAX * 2];  // fp16 scaled hidden L2 (gather table)
__device__ uint4  g_agg1[NMAX * 2];  // fp16 accumulator L1 (init = g_h row)
__device__ uint4  g_agg2[NMAX * 2];  // fp16 accumulator L2 (init = g_h2 row)

// ---- f32x2 packed-math helpers (sm_103a) ----
__device__ __forceinline__ unsigned long long f2_fma(
    unsigned long long a, unsigned long long b, unsigned long long c) {
    unsigned long long d;
    asm("fma.rn.f32x2 %0, %1, %2, %3;" : "=l"(d) : "l"(a), "l"(b), "l"(c));
    return d;
}
__device__ __forceinline__ unsigned long long f2_add(
    unsigned long long a, unsigned long long b) {
    unsigned long long d;
    asm("add.rn.f32x2 %0, %1, %2;" : "=l"(d) : "l"(a), "l"(b));
    return d;
}
__device__ __forceinline__ unsigned long long f2_pack(float lo, float hi) {
    unsigned long long d;
    asm("mov.b64 %0, {%1, %2};" : "=l"(d) : "f"(lo), "f"(hi));
    return d;
}

// ---------------------------------------------------------------
__global__ void k_init(const int* __restrict__ ei, int N) {
    int i = blockIdx.x * blockDim.x + threadIdx.x;
    if (i < N) g_deg[i] = 0;
    if (i == 0) {
        int any = 0;
        #pragma unroll
        for (int q = 1; q < 256; q += 2) any |= ei[q];
        g_is64 = (any == 0) ? 1 : 0;
    }
}

// Normalize edges to packed int2 and count in-degree (dst side).
__global__ __launch_bounds__(256) void k_convert(const void* __restrict__ ei, int E) {
    int e = blockIdx.x * blockDim.x + threadIdx.x;
    if (e >= E) return;
    int s, d;
    if (g_is64) {
        const long long* p = (const long long*)ei;
        s = (int)p[e];
        d = (int)p[(long long)E + e];
    } else {
        const int* p = (const int*)ei;
        s = p[e];
        d = p[E + e];
    }
    g_edge[e] = make_int2(s, d);
    atomicAdd(&g_deg[d], 1);
}

// ---------------------------------------------------------------
// GEMM1 (raw, no dinv scaling — runs concurrently with k_convert):
// g_hraw[i,:] = x[i,:] @ W1.  Exact R3/R7 proven structure.
#define WPITCH 513
__global__ __launch_bounds__(256, 2) void k_gemm1raw(
    const float* __restrict__ x, const float* __restrict__ W1, int N)
{
    __shared__ unsigned long long wS[8 * WPITCH];
    {
        const unsigned long long* gw = (const unsigned long long*)W1;
        for (int idx = threadIdx.x; idx < FDIM * 8; idx += 256) {
            int k = idx >> 3, j2 = idx & 7;
            wS[j2 * WPITCH + k] = gw[idx];
        }
    }
    __syncthreads();

    int warp = threadIdx.x >> 5;
    int lane = threadIdx.x & 31;
    int r0 = blockIdx.x * 32 + warp * 4;

    unsigned long long acc[4][8];
    #pragma unroll
    for (int r = 0; r < 4; r++)
        #pragma unroll
        for (int j = 0; j < 8; j++) acc[r][j] = 0ull;

    bool v0 = (r0 + 0) < N, v1 = (r0 + 1) < N, v2 = (r0 + 2) < N, v3 = (r0 + 3) < N;
    const float* x0p = x + (size_t)(r0 + 0) * FDIM + lane;
    const float* x1p = x + (size_t)(r0 + 1) * FDIM + lane;
    const float* x2p = x + (size_t)(r0 + 2) * FDIM + lane;
    const float* x3p = x + (size_t)(r0 + 3) * FDIM + lane;

    #pragma unroll 4
    for (int i = 0; i < 16; i++) {
        int k = lane + 32 * i;
        float x0 = v0 ? x0p[32 * i] : 0.0f;
        float x1 = v1 ? x1p[32 * i] : 0.0f;
        float x2 = v2 ? x2p[32 * i] : 0.0f;
        float x3 = v3 ? x3p[32 * i] : 0.0f;
        unsigned long long p0 = f2_pack(x0, x0);
        unsigned long long p1 = f2_pack(x1, x1);
        unsigned long long p2 = f2_pack(x2, x2);
        unsigned long long p3 = f2_pack(x3, x3);
        #pragma unroll
        for (int j = 0; j < 8; j++) {
            unsigned long long wv = wS[j * WPITCH + k];
            acc[0][j] = f2_fma(p0, wv, acc[0][j]);
            acc[1][j] = f2_fma(p1, wv, acc[1][j]);
            acc[2][j] = f2_fma(p2, wv, acc[2][j]);
            acc[3][j] = f2_fma(p3, wv, acc[3][j]);
        }
    }

    unsigned long long v[32];
    #pragma unroll
    for (int r = 0; r < 4; r++)
        #pragma unroll
        for (int j = 0; j < 8; j++) v[r * 8 + j] = acc[r][j];

    #pragma unroll
    for (int s = 0; s < 5; s++) {
        const int m = 1 << s;
        const int half = 16 >> s;
        bool up = (lane & m) != 0;
        #pragma unroll
        for (int q = 0; q < 16; q++) {
            if (q < half) {
                unsigned long long keep = up ? v[q + half] : v[q];
                unsigned long long mine = up ? v[q] : v[q + half];
                unsigned long long got = __shfl_xor_sync(0xffffffffu, mine, m);
                v[q] = f2_add(keep, got);
            }
        }
    }

    int p = ((lane & 1) << 4) | ((lane & 2) << 2) | (lane & 4) |
            ((lane & 8) >> 2) | ((lane & 16) >> 4);
    int r = p >> 3, j2 = p & 7;
    int row = r0 + r;
    if (row < N) {
        ((unsigned long long*)g_hraw)[(size_t)row * 8 + j2] =
            v[0];   // raw fp32 pair
    }
}

// ---------------------------------------------------------------
// Scale epilogue (after join): hs = fp16(dinv * hraw), dinv computed
// inline from deg. Writes gather table g_h and accumulator init g_agg1.
__global__ void k_scale(int N) {
    int idx = blockIdx.x * blockDim.x + threadIdx.x;   // half2 index
    if (idx >= N * 8) return;
    int i = idx >> 3;
    float dv = rsqrtf((float)(g_deg[i] + 1));
    float2 rf = g_hraw[idx];
    rf.x *= dv; rf.y *= dv;
    __half2 hv = __float22half2_rn(rf);
    ((__half2*)g_h)[idx] = hv;
    ((__half2*)g_agg1)[idx] = hv;
}

// ---------------------------------------------------------------
// Edge propagation: 2 threads per edge, one 16B chunk (8 halves) each.
__global__ __launch_bounds__(256) void k_prop(int E, int layer) {
    int t = blockIdx.x * blockDim.x + threadIdx.x;
    int e = t >> 1;
    if (e >= E) return;
    int c = t & 1;
    const uint4* hin = layer ? g_h2 : g_h;
    uint4* out = layer ? g_agg2 : g_agg1;

    int2 sd = g_edge[e];
    uint4 v = hin[(size_t)sd.x * 2 + c];
    uint4* p = out + (size_t)sd.y * 2 + c;
    asm volatile("red.global.add.noftz.v4.f16x2 [%0], {%1, %2, %3, %4};"
                 :: "l"(p), "r"(v.x), "r"(v.y), "r"(v.z), "r"(v.w)
                 : "memory");
}

// ---------------------------------------------------------------
// Mid layer, per 16B chunk: out1 = relu(dinv*agg1 + b1); hs2 = dinv*out1
__global__ void k_mid(const float* __restrict__ b1, int N) {
    int idx = blockIdx.x * blockDim.x + threadIdx.x;   // chunk index
    if (idx >= N * 2) return;
    int i = idx >> 1;
    int c = idx & 1;
    float dv = rsqrtf((float)(g_deg[i] + 1));
    uint4 a = g_agg1[idx];
    float2 f0 = __half22float2(*(__half2*)&a.x);
    float2 f1 = __half22float2(*(__half2*)&a.y);
    float2 f2v = __half22float2(*(__half2*)&a.z);
    float2 f3 = __half22float2(*(__half2*)&a.w);
    const float4* b4 = (const float4*)b1;
    float4 bb0 = b4[c * 2 + 0];
    float4 bb1 = b4[c * 2 + 1];
    float2 r0, r1, r2, r3;
    r0.x = fmaxf(dv * f0.x + bb0.x, 0.f) * dv;
    r0.y = fmaxf(dv * f0.y + bb0.y, 0.f) * dv;
    r1.x = fmaxf(dv * f1.x + bb0.z, 0.f) * dv;
    r1.y = fmaxf(dv * f1.y + bb0.w, 0.f) * dv;
    r2.x = fmaxf(dv * f2v.x + bb1.x, 0.f) * dv;
    r2.y = fmaxf(dv * f2v.y + bb1.y, 0.f) * dv;
    r3.x = fmaxf(dv * f3.x + bb1.z, 0.f) * dv;
    r3.y = fmaxf(dv * f3.y + bb1.w, 0.f) * dv;
    uint4 o;
    *(__half2*)&o.x = __float22half2_rn(r0);
    *(__half2*)&o.y = __float22half2_rn(r1);
    *(__half2*)&o.z = __float22half2_rn(r2);
    *(__half2*)&o.w = __float22half2_rn(r3);
    g_h2[idx] = o;
    g_agg2[idx] = o;
}

// ---------------------------------------------------------------
// Output: logits = (dinv[i]*agg2[i,:]) @ W2 + b2 ; out = softmax
// d_out[0:N*40) = softmax ; d_out[N*40:2N*40) = logits
__global__ __launch_bounds__(256) void k_out(
    const float* __restrict__ W2, const float* __restrict__ b2,
    float* __restrict__ dout, int N, int write_h)
{
    __shared__ float w[HDIM * CDIM];
    __shared__ float bs[CDIM];
    for (int i = threadIdx.x; i < HDIM * CDIM; i += blockDim.x) w[i] = W2[i];
    if (threadIdx.x < CDIM) bs[threadIdx.x] = b2[threadIdx.x];
    __syncthreads();

    int i = blockIdx.x * blockDim.x + threadIdx.x;
    if (i >= N) return;

    float dv = rsqrtf((float)(g_deg[i] + 1));
    float row[HDIM];
    #pragma unroll
    for (int c = 0; c < 2; c++) {
        uint4 a = g_agg2[(size_t)i * 2 + c];
        float2 f0 = __half22float2(*(__half2*)&a.x);
        float2 f1 = __half22float2(*(__half2*)&a.y);
        float2 f2v = __half22float2(*(__half2*)&a.z);
        float2 f3 = __half22float2(*(__half2*)&a.w);
        row[c * 8 + 0] = f0.x * dv; row[c * 8 + 1] = f0.y * dv;
        row[c * 8 + 2] = f1.x * dv; row[c * 8 + 3] = f1.y * dv;
        row[c * 8 + 4] = f2v.x * dv; row[c * 8 + 5] = f2v.y * dv;
        row[c * 8 + 6] = f3.x * dv; row[c * 8 + 7] = f3.y * dv;
    }

    float logit[CDIM];
    #pragma unroll
    for (int j = 0; j < CDIM; j++) logit[j] = bs[j];
    #pragma unroll
    for (int k = 0; k < HDIM; k++) {
        float v = row[k];
        const float* wr = &w[k * CDIM];
        #pragma unroll
        for (int j = 0; j < CDIM; j++) logit[j] += v * wr[j];
    }

    float mx = logit[0];
    #pragma unroll
    for (int j = 1; j < CDIM; j++) mx = fmaxf(mx, logit[j]);
    float sum = 0.0f;
    #pragma unroll
    for (int j = 0; j < CDIM; j++) sum += __expf(logit[j] - mx);
    float inv = 1.0f / sum;

    float* so = dout + (size_t)i * CDIM;
    #pragma unroll
    for (int j = 0; j < CDIM; j++) so[j] = __expf(logit[j] - mx) * inv;

    if (write_h) {
        float* ho = dout + (size_t)N * CDIM + (size_t)i * CDIM;
        #pragma unroll
        for (int j = 0; j < CDIM; j++) ho[j] = logit[j];
    }
}

// ---------------------------------------------------------------
extern "C" void kernel_launch(void* const* d_in, const int* in_sizes, int n_in,
                              void* d_out, int out_size)
{
    // metadata order: x, edge_index, num_nodes, W1, b1, W2, b2
    const float* x  = (const float*)d_in[0];
    const void*  ei = d_in[1];
    const float* W1 = (const float*)d_in[3];
    const float* b1 = (const float*)d_in[4];
    const float* W2 = (const float*)d_in[5];
    const float* b2 = (const float*)d_in[6];
    float* out = (float*)d_out;

    int N = in_sizes[0] / FDIM;
    int E = in_sizes[1] / 2;
    if (N > NMAX) N = NMAX;
    if (E > EMAX) E = EMAX;
    int write_h = (out_size >= 2 * N * CDIM) ? 1 : 0;

    const int B = 256;

    // Fork-join: edge processing (L2/atomic-bound) runs concurrently
    // with the raw GEMM (SM-bound) on a second stream. Host objects
    // only (stream/events) — no device allocation.
    cudaStream_t s2;
    cudaEvent_t evFork, evJoin;
    cudaStreamCreateWithFlags(&s2, cudaStreamNonBlocking);
    cudaEventCreateWithFlags(&evFork, cudaEventDisableTiming);
    cudaEventCreateWithFlags(&evJoin, cudaEventDisableTiming);

    cudaEventRecord(evFork, 0);
    cudaStreamWaitEvent(s2, evFork, 0);

    // branch B (s2): raw GEMM, independent of edges
    k_gemm1raw<<<(N + 31) / 32, 256, 0, s2>>>(x, W1, N);
    cudaEventRecord(evJoin, s2);

    // branch A (main stream): edge decode + degree
    k_init<<<(N + B - 1) / B, B>>>((const int*)ei, N);
    k_convert<<<(E + B - 1) / B, B>>>(ei, E);

    // join
    cudaStreamWaitEvent(0, evJoin, 0);

    k_scale<<<(N * 8 + B - 1) / B, B>>>(N);

    k_prop<<<((size_t)E * 2 + B - 1) / B, B>>>(E, 0);
    k_mid<<<(N * 2 + B - 1) / B, B>>>(b1, N);
    k_prop<<<((size_t)E * 2 + B - 1) / B, B>>>(E, 1);

    k_out<<<(N + B - 1) / B, B>>>(W2, b2, out, N, write_h);

    cudaStreamDestroy(s2);      // deferred; safe during capture teardown
    cudaEventDestroy(evFork);
    cudaEventDestroy(evJoin);
}